// round 7
// baseline (speedup 1.0000x reference)
#include <cuda_runtime.h>
#include <cuda_bf16.h>
#include <cstdint>

#define NROW 8192
#define DDIM 128
#define THREADS 256
#define NTILE 64                      /* 8192 / 128 */

// Scratch: bf16 copy of z and fp32 squared norms.
__device__ __nv_bfloat16 g_zbf[NROW * DDIM];
__device__ float g_sq[NROW];

// ---------------------------------------------------------------------------
// SMEM layout. Row stride 272B (128 bf16 + 8 pad) keeps ldmatrix conflict-free.
// ---------------------------------------------------------------------------
#define ROWB 272
#define SM_A 0
#define SM_B (128 * ROWB)            /* 34816 */
#define SM_SQA (2 * 128 * ROWB)      /* 69632 */
#define SM_SQB (SM_SQA + 512)
#define SM_FLAG (SM_SQB + 512)
#define SMEM_BYTES (SM_FLAG + 16)    /* 70672 */

__device__ __forceinline__ uint32_t smem_u32(const void* p) {
    uint32_t a;
    asm("{ .reg .u64 t; cvta.to.shared.u64 t, %1; cvt.u32.u64 %0, t; }"
        : "=r"(a) : "l"(p));
    return a;
}

__device__ __forceinline__ void ldsm4(uint32_t addr, uint32_t r[4]) {
    asm volatile("ldmatrix.sync.aligned.m8n8.x4.shared.b16 {%0,%1,%2,%3}, [%4];"
                 : "=r"(r[0]), "=r"(r[1]), "=r"(r[2]), "=r"(r[3]) : "r"(addr));
}

__device__ __forceinline__ void mma16816(float c[4], const uint32_t a[4],
                                         uint32_t b0, uint32_t b1) {
    asm volatile(
        "mma.sync.aligned.m16n8k16.row.col.f32.bf16.bf16.f32 "
        "{%0,%1,%2,%3}, {%4,%5,%6,%7}, {%8,%9}, {%0,%1,%2,%3};"
        : "+f"(c[0]), "+f"(c[1]), "+f"(c[2]), "+f"(c[3])
        : "r"(a[0]), "r"(a[1]), "r"(a[2]), "r"(a[3]), "r"(b0), "r"(b1));
}

// ---------------------------------------------------------------------------
// Prep: bf16 convert + squared norms (tiny).
// ---------------------------------------------------------------------------
__global__ __launch_bounds__(128)
void prep_kernel(const float* __restrict__ z) {
    int row = blockIdx.x, t = threadIdx.x;
    float v = z[row * DDIM + t];
    g_zbf[row * DDIM + t] = __float2bfloat16(v);
    float s = v * v;
    #pragma unroll
    for (int off = 16; off > 0; off >>= 1) s += __shfl_xor_sync(~0u, s, off);
    __shared__ float ws[4];
    if ((t & 31) == 0) ws[t >> 5] = s;
    __syncthreads();
    if (t == 0) g_sq[row] = ws[0] + ws[1] + ws[2] + ws[3];
}

// ---------------------------------------------------------------------------
// Main kernel: upper-triangular 128x128 tiles via mma.sync bf16.
// Value-free warp regions (the common case) take a fully coalesced zero path
// for BOTH the direct and mirror tiles; fragment scatter only where values live.
// ---------------------------------------------------------------------------
extern __shared__ char smem[];

__global__ __launch_bounds__(THREADS, 2)
void pairsim_mma(float* __restrict__ out) {
    // Triangular decode: blockIdx.x -> (by, bx) with bx >= by.
    int id = blockIdx.x;
    int by = (int)((2.0f * NTILE + 1.0f
                    - sqrtf((2.0f * NTILE + 1.0f) * (2.0f * NTILE + 1.0f)
                            - 8.0f * (float)id)) * 0.5f);
    while (by > 0 && by * NTILE - (by * (by - 1)) / 2 > id) --by;
    while ((by + 1) * NTILE - ((by + 1) * by) / 2 <= id) ++by;
    const int bx = by + (id - (by * NTILE - (by * (by - 1)) / 2));

    const int brow = by * 128, bcol = bx * 128;
    const uint32_t sb = smem_u32(smem);
    const int tid = threadIdx.x, wid = tid >> 5, lane = tid & 31;
    const int wr = wid & 3, wc = wid >> 2;
    const bool diag = (bx == by);

    float* SQA = (float*)(smem + SM_SQA);
    float* SQB = (float*)(smem + SM_SQB);
    int* FLAG = (int*)(smem + SM_FLAG);
    if (tid == 0) *FLAG = 0;
    if (tid < 128) SQA[tid] = g_sq[brow + tid];
    else           SQB[tid - 128] = g_sq[bcol + tid - 128];

    // Load A (rows brow..+127) and B (rows bcol..+127) tiles, 16B chunks.
    #pragma unroll
    for (int it = 0; it < 8; ++it) {
        int idx = tid + it * THREADS;      // 0..2047
        int r = idx >> 4, kc = (idx & 15) << 3;
        *(uint4*)(smem + SM_A + r * ROWB + kc * 2) =
            *(const uint4*)&g_zbf[(size_t)(brow + r) * DDIM + kc];
        *(uint4*)(smem + SM_B + r * ROWB + kc * 2) =
            *(const uint4*)&g_zbf[(size_t)(bcol + r) * DDIM + kc];
    }
    __syncthreads();

    // ldmatrix lane base addresses.
    const uint32_t aBase = sb + SM_A + (wr * 32 + (lane & 15)) * ROWB
                         + ((lane >> 4) << 4);
    const uint32_t bBase = sb + SM_B
                         + (wc * 64 + ((lane & 7) | ((lane >> 4) << 3))) * ROWB
                         + (((lane >> 3) & 1) << 4);

    float acc[2][8][4];
    #pragma unroll
    for (int mt = 0; mt < 2; ++mt)
        #pragma unroll
        for (int nt = 0; nt < 8; ++nt)
            #pragma unroll
            for (int c = 0; c < 4; ++c) acc[mt][nt][c] = 0.0f;

    #pragma unroll
    for (int ks = 0; ks < 8; ++ks) {
        uint32_t aF[2][4], bF[4][4];
        ldsm4(aBase + ks * 32, aF[0]);
        ldsm4(aBase + 16 * ROWB + ks * 32, aF[1]);
        #pragma unroll
        for (int p = 0; p < 4; ++p) ldsm4(bBase + p * 16 * ROWB + ks * 32, bF[p]);
        #pragma unroll
        for (int mt = 0; mt < 2; ++mt)
            #pragma unroll
            for (int p = 0; p < 4; ++p) {
                mma16816(acc[mt][2 * p],     aF[mt], bF[p][0], bF[p][1]);
                mma16816(acc[mt][2 * p + 1], aF[mt], bF[p][2], bF[p][3]);
            }
    }

    // Epilogue: d2 = sqa + sqb - 2*gram.
    const int qr = lane >> 2;            // 0..7
    const int qc = (lane & 3) << 1;      // 0,2,4,6
    float sqa_r[4], sqb_c[16];
    #pragma unroll
    for (int mt = 0; mt < 2; ++mt)
        #pragma unroll
        for (int h = 0; h < 2; ++h)
            sqa_r[mt * 2 + h] = SQA[wr * 32 + mt * 16 + qr + h * 8];
    #pragma unroll
    for (int nt = 0; nt < 8; ++nt) {
        sqb_c[2 * nt]     = SQB[wc * 64 + nt * 8 + qc];
        sqb_c[2 * nt + 1] = SQB[wc * 64 + nt * 8 + qc + 1];
    }

    float vmin = 3.4e38f;
    #pragma unroll
    for (int mt = 0; mt < 2; ++mt)
        #pragma unroll
        for (int nt = 0; nt < 8; ++nt)
            #pragma unroll
            for (int c = 0; c < 4; ++c) {
                float s = sqa_r[mt * 2 + (c >> 1)] + sqb_c[2 * nt + (c & 1)];
                float d2 = fmaf(-2.0f, acc[mt][nt][c], s);
                acc[mt][nt][c] = d2;
                vmin = fminf(vmin, d2);
            }

    // Does this warp's 32x64 region contain any representable value?
    const bool crossDiag = diag && ((wr >> 1) == wc);
    const bool anyv = crossDiag | __any_sync(0xffffffffu, vmin < 88.0f);

    if (anyv) {
        // Rare path: compute exp and scatter per-fragment (direct tile).
        #pragma unroll
        for (int mt = 0; mt < 2; ++mt)
            #pragma unroll
            for (int nt = 0; nt < 8; ++nt)
                #pragma unroll
                for (int c = 0; c < 4; ++c) {
                    float d2 = fmaxf(acc[mt][nt][c], 0.0f);
                    float v = (d2 < 88.0f) ? __expf(-d2) : 0.0f;
                    int m = brow + wr * 32 + mt * 16 + qr + ((c >> 1) << 3);
                    int n = bcol + wc * 64 + nt * 8 + qc + (c & 1);
                    if (m == n) v = 1.0f;     // exact diagonal
                    acc[mt][nt][c] = v;
                }
        if (!diag && lane == 0) *FLAG = 1;    // benign racy OR

        #pragma unroll
        for (int mt = 0; mt < 2; ++mt)
            #pragma unroll
            for (int h = 0; h < 2; ++h) {
                int m_loc = wr * 32 + mt * 16 + qr + h * 8;
                size_t rowp = (size_t)(brow + m_loc) * NROW + bcol + wc * 64;
                #pragma unroll
                for (int nt = 0; nt < 8; ++nt)
                    *(float2*)&out[rowp + nt * 8 + qc] =
                        make_float2(acc[mt][nt][2 * h], acc[mt][nt][2 * h + 1]);
            }
    } else {
        // Common path: coalesced float4 zero-fill of this warp's 32x64 region.
        // Each iter: 32 lanes x 16B = 2 full 256B rows.
        const float4 zero = make_float4(0.f, 0.f, 0.f, 0.f);
        const size_t base = (size_t)(brow + wr * 32) * NROW + bcol + wc * 64;
        const int rofs = lane >> 4;           // 0..1
        const int c4 = (lane & 15) << 2;      // 0..60
        #pragma unroll
        for (int it = 0; it < 16; ++it)
            *(float4*)&out[base + (size_t)(it * 2 + rofs) * NROW + c4] = zero;
    }

    // Mirror tile (rows bcol.., cols brow..): coalesced zero-fill; zeros are
    // symmetric so no transpose. Sole owner of that tile -> no races.
    if (!diag) {
        const float4 zero = make_float4(0.f, 0.f, 0.f, 0.f);
        #pragma unroll
        for (int it = 0; it < 16; ++it) {
            int idx = tid + it * THREADS;      // 0..4095
            int n = idx >> 5, cc = (idx & 31) << 2;
            *(float4*)&out[(size_t)(bcol + n) * NROW + brow + cc] = zero;
        }
        __syncthreads();
        // Rare: patch actual values into the mirror via scalar scatter.
        if (*FLAG && anyv) {
            #pragma unroll
            for (int mt = 0; mt < 2; ++mt)
                #pragma unroll
                for (int nt = 0; nt < 8; ++nt)
                    #pragma unroll
                    for (int c = 0; c < 4; ++c) {
                        int m = brow + wr * 32 + mt * 16 + qr + ((c >> 1) << 3);
                        int n = bcol + wc * 64 + nt * 8 + qc + (c & 1);
                        out[(size_t)n * NROW + m] = acc[mt][nt][c];
                    }
        }
    }
}

// ---------------------------------------------------------------------------
extern "C" void kernel_launch(void* const* d_in, const int* in_sizes, int n_in,
                              void* d_out, int out_size) {
    const float* z = (const float*)d_in[0];
    float* out = (float*)d_out;
    (void)in_sizes; (void)n_in; (void)out_size;

    cudaFuncSetAttribute(pairsim_mma,
                         cudaFuncAttributeMaxDynamicSharedMemorySize, SMEM_BYTES);

    prep_kernel<<<NROW, 128>>>(z);
    const int ntri = NTILE * (NTILE + 1) / 2;    // 2080
    pairsim_mma<<<ntri, THREADS, SMEM_BYTES>>>(out);
}

// round 8
// speedup vs baseline: 1.2231x; 1.2231x over previous
#include <cuda_runtime.h>
#include <cuda_bf16.h>
#include <cstdint>

#define NROW 8192
#define DDIM 128
#define THREADS 256
#define NTILE 64                      /* 8192 / 128 */

// Scratch: bf16 copy of z and fp32 squared norms.
__device__ __nv_bfloat16 g_zbf[NROW * DDIM];
__device__ float g_sq[NROW];

// ---------------------------------------------------------------------------
// SMEM layout. Row stride 272B (128 bf16 + 8 pad) keeps ldmatrix conflict-free.
// ---------------------------------------------------------------------------
#define ROWB 272
#define SM_A 0
#define SM_B (128 * ROWB)            /* 34816 */
#define SM_SQA (2 * 128 * ROWB)      /* 69632 */
#define SM_SQB (SM_SQA + 512)
#define SMEM_BYTES (SM_SQB + 512)    /* 70656 */

__device__ __forceinline__ uint32_t smem_u32(const void* p) {
    uint32_t a;
    asm("{ .reg .u64 t; cvta.to.shared.u64 t, %1; cvt.u32.u64 %0, t; }"
        : "=r"(a) : "l"(p));
    return a;
}

__device__ __forceinline__ void ldsm4(uint32_t addr, uint32_t r[4]) {
    asm volatile("ldmatrix.sync.aligned.m8n8.x4.shared.b16 {%0,%1,%2,%3}, [%4];"
                 : "=r"(r[0]), "=r"(r[1]), "=r"(r[2]), "=r"(r[3]) : "r"(addr));
}

__device__ __forceinline__ void mma16816(float c[4], const uint32_t a[4],
                                         uint32_t b0, uint32_t b1) {
    asm volatile(
        "mma.sync.aligned.m16n8k16.row.col.f32.bf16.bf16.f32 "
        "{%0,%1,%2,%3}, {%4,%5,%6,%7}, {%8,%9}, {%0,%1,%2,%3};"
        : "+f"(c[0]), "+f"(c[1]), "+f"(c[2]), "+f"(c[3])
        : "r"(a[0]), "r"(a[1]), "r"(a[2]), "r"(a[3]), "r"(b0), "r"(b1));
}

// ---------------------------------------------------------------------------
// Prep: bf16 convert + squared norms. 2 rows per 256-thread block.
// ---------------------------------------------------------------------------
__global__ __launch_bounds__(256)
void prep_kernel(const float* __restrict__ z) {
    int row = blockIdx.x * 2 + (threadIdx.x >> 7);
    int t = threadIdx.x & 127;
    float v = z[row * DDIM + t];
    g_zbf[row * DDIM + t] = __float2bfloat16(v);
    float s = v * v;
    #pragma unroll
    for (int off = 16; off > 0; off >>= 1) s += __shfl_xor_sync(~0u, s, off);
    __shared__ float ws[8];
    int w = threadIdx.x >> 5;
    if ((t & 31) == 0) ws[w] = s;
    __syncthreads();
    if (t == 0) {
        int b = (w >> 2) << 2;
        g_sq[row] = ws[b] + ws[b + 1] + ws[b + 2] + ws[b + 3];
    }
}

// ---------------------------------------------------------------------------
// Main kernel: upper-triangular 128x128 tiles via mma.sync bf16.
// ALL output bytes (direct + mirror tiles) are zero-filled at the TOP of the
// kernel — dependency-free stores that overlap the LDG latency and the whole
// MMA phase. After the MMA, rare value-bearing warps patch their fragments.
// The post-STS __syncthreads() orders zero-fill vs patches at CTA scope.
// ---------------------------------------------------------------------------
extern __shared__ char smem[];

__global__ __launch_bounds__(THREADS, 2)
void pairsim_mma(float* __restrict__ out) {
    // Triangular decode: blockIdx.x -> (by, bx) with bx >= by.
    int id = blockIdx.x;
    int by = (int)((2.0f * NTILE + 1.0f
                    - sqrtf((2.0f * NTILE + 1.0f) * (2.0f * NTILE + 1.0f)
                            - 8.0f * (float)id)) * 0.5f);
    while (by > 0 && by * NTILE - (by * (by - 1)) / 2 > id) --by;
    while ((by + 1) * NTILE - ((by + 1) * by) / 2 <= id) ++by;
    const int bx = by + (id - (by * NTILE - (by * (by - 1)) / 2));

    const int brow = by * 128, bcol = bx * 128;
    const uint32_t sb = smem_u32(smem);
    const int tid = threadIdx.x, wid = tid >> 5, lane = tid & 31;
    const int wr = wid & 3, wc = wid >> 2;
    const bool diag = (bx == by);

    float* SQA = (float*)(smem + SM_SQA);
    float* SQB = (float*)(smem + SM_SQB);
    if (tid < 128) SQA[tid] = g_sq[brow + tid];
    else           SQB[tid - 128] = g_sq[bcol + tid - 128];

    // Tile loads (LDG -> STS), issued first so their latency overlaps stores.
    #pragma unroll
    for (int it = 0; it < 8; ++it) {
        int idx = tid + it * THREADS;      // 0..2047
        int r = idx >> 4, kc = (idx & 15) << 3;
        *(uint4*)(smem + SM_A + r * ROWB + kc * 2) =
            *(const uint4*)&g_zbf[(size_t)(brow + r) * DDIM + kc];
        *(uint4*)(smem + SM_B + r * ROWB + kc * 2) =
            *(const uint4*)&g_zbf[(size_t)(bcol + r) * DDIM + kc];
    }

    // Dependency-free zero-fill of BOTH output tiles (the common-case bytes).
    {
        const float4 zero = make_float4(0.f, 0.f, 0.f, 0.f);
        const int n0 = tid >> 5;             // row stride 8 per iter
        const int cc = (tid & 31) << 2;
        #pragma unroll
        for (int it = 0; it < 16; ++it) {
            int n = n0 + it * 8;
            *(float4*)&out[(size_t)(brow + n) * NROW + bcol + cc] = zero;
        }
        if (!diag) {
            #pragma unroll
            for (int it = 0; it < 16; ++it) {
                int n = n0 + it * 8;
                *(float4*)&out[(size_t)(bcol + n) * NROW + brow + cc] = zero;
            }
        }
    }

    __syncthreads();   // tiles ready in smem; also orders zero-fill vs patches

    // ldmatrix lane base addresses.
    const uint32_t aBase = sb + SM_A + (wr * 32 + (lane & 15)) * ROWB
                         + ((lane >> 4) << 4);
    const uint32_t bBase = sb + SM_B
                         + (wc * 64 + ((lane & 7) | ((lane >> 4) << 3))) * ROWB
                         + (((lane >> 3) & 1) << 4);

    float acc[2][8][4];
    #pragma unroll
    for (int mt = 0; mt < 2; ++mt)
        #pragma unroll
        for (int nt = 0; nt < 8; ++nt)
            #pragma unroll
            for (int c = 0; c < 4; ++c) acc[mt][nt][c] = 0.0f;

    #pragma unroll
    for (int ks = 0; ks < 8; ++ks) {
        uint32_t aF[2][4], bF[4][4];
        ldsm4(aBase + ks * 32, aF[0]);
        ldsm4(aBase + 16 * ROWB + ks * 32, aF[1]);
        #pragma unroll
        for (int p = 0; p < 4; ++p) ldsm4(bBase + p * 16 * ROWB + ks * 32, bF[p]);
        #pragma unroll
        for (int mt = 0; mt < 2; ++mt)
            #pragma unroll
            for (int p = 0; p < 4; ++p) {
                mma16816(acc[mt][2 * p],     aF[mt], bF[p][0], bF[p][1]);
                mma16816(acc[mt][2 * p + 1], aF[mt], bF[p][2], bF[p][3]);
            }
    }

    // Epilogue: d2 = sqa + sqb - 2*gram.
    const int qr = lane >> 2;            // 0..7
    const int qc = (lane & 3) << 1;      // 0,2,4,6
    float sqa_r[4], sqb_c[16];
    #pragma unroll
    for (int mt = 0; mt < 2; ++mt)
        #pragma unroll
        for (int h = 0; h < 2; ++h)
            sqa_r[mt * 2 + h] = SQA[wr * 32 + mt * 16 + qr + h * 8];
    #pragma unroll
    for (int nt = 0; nt < 8; ++nt) {
        sqb_c[2 * nt]     = SQB[wc * 64 + nt * 8 + qc];
        sqb_c[2 * nt + 1] = SQB[wc * 64 + nt * 8 + qc + 1];
    }

    float vmin = 3.4e38f;
    #pragma unroll
    for (int mt = 0; mt < 2; ++mt)
        #pragma unroll
        for (int nt = 0; nt < 8; ++nt)
            #pragma unroll
            for (int c = 0; c < 4; ++c) {
                float s = sqa_r[mt * 2 + (c >> 1)] + sqb_c[2 * nt + (c & 1)];
                float d2 = fmaf(-2.0f, acc[mt][nt][c], s);
                acc[mt][nt][c] = d2;
                vmin = fminf(vmin, d2);
            }

    // Rare: this warp's 32x64 region holds a representable value (or diag 1s).
    const bool crossDiag = diag && ((wr >> 1) == wc);
    const bool anyv = crossDiag | __any_sync(0xffffffffu, vmin < 88.0f);
    if (!anyv) return;                   // zeros already in place

    #pragma unroll
    for (int mt = 0; mt < 2; ++mt)
        #pragma unroll
        for (int nt = 0; nt < 8; ++nt)
            #pragma unroll
            for (int c = 0; c < 4; ++c) {
                float d2 = fmaxf(acc[mt][nt][c], 0.0f);
                float v = (d2 < 88.0f) ? __expf(-d2) : 0.0f;
                int m = brow + wr * 32 + mt * 16 + qr + ((c >> 1) << 3);
                int n = bcol + wc * 64 + nt * 8 + qc + (c & 1);
                if (m == n) v = 1.0f;    // exact diagonal
                acc[mt][nt][c] = v;
            }

    // Patch direct region (fragment-layout float2 stores).
    #pragma unroll
    for (int mt = 0; mt < 2; ++mt)
        #pragma unroll
        for (int h = 0; h < 2; ++h) {
            int m_loc = wr * 32 + mt * 16 + qr + h * 8;
            size_t rowp = (size_t)(brow + m_loc) * NROW + bcol + wc * 64;
            #pragma unroll
            for (int nt = 0; nt < 8; ++nt)
                *(float2*)&out[rowp + nt * 8 + qc] =
                    make_float2(acc[mt][nt][2 * h], acc[mt][nt][2 * h + 1]);
        }

    // Patch mirror region (scalar transposed scatter).
    if (!diag) {
        #pragma unroll
        for (int mt = 0; mt < 2; ++mt)
            #pragma unroll
            for (int nt = 0; nt < 8; ++nt)
                #pragma unroll
                for (int c = 0; c < 4; ++c) {
                    int m = brow + wr * 32 + mt * 16 + qr + ((c >> 1) << 3);
                    int n = bcol + wc * 64 + nt * 8 + qc + (c & 1);
                    out[(size_t)n * NROW + m] = acc[mt][nt][c];
                }
    }
}

// ---------------------------------------------------------------------------
extern "C" void kernel_launch(void* const* d_in, const int* in_sizes, int n_in,
                              void* d_out, int out_size) {
    const float* z = (const float*)d_in[0];
    float* out = (float*)d_out;
    (void)in_sizes; (void)n_in; (void)out_size;

    cudaFuncSetAttribute(pairsim_mma,
                         cudaFuncAttributeMaxDynamicSharedMemorySize, SMEM_BYTES);

    prep_kernel<<<NROW / 2, 256>>>(z);
    const int ntri = NTILE * (NTILE + 1) / 2;    // 2080
    pairsim_mma<<<ntri, THREADS, SMEM_BYTES>>>(out);
}